// round 4
// baseline (speedup 1.0000x reference)
#include <cuda_runtime.h>
#include <math.h>
#include <stdint.h>

// ---------------------------------------------------------------------------
// Problem constants (fixed by the reference)
// ---------------------------------------------------------------------------
constexpr int T_TOK = 4096;           // B*S tokens
constexpr int HDIM  = 2048;           // hidden dim
constexpr int FMOE  = 1024;           // routed expert ffn dim
constexpr int FSH   = 2048;           // shared expert ffn dim
constexpr int NEXP  = 16;
constexpr int TOPK  = 4;
constexpr int NGRP  = 4;
constexpr int EPG   = NEXP / NGRP;    // 4 experts per group
constexpr int NASS  = T_TOK * TOPK;   // 16384 assignments
constexpr float RSCALE = 2.5f;

// ---------------------------------------------------------------------------
// Device scratch (static globals: allocation-free per the harness rules)
// ---------------------------------------------------------------------------
__device__ int   g_counts[NEXP];
__device__ int   g_fill[NEXP];
__device__ int   g_offsets[NEXP + 1];
__device__ int   g_topk_idx[NASS];
__device__ float g_topk_w[NASS];
__device__ int   g_tk[NASS];                       // packed t*4+k per slot
__device__ float g_w[NASS];                        // routing weight per slot
__device__ float g_act[(size_t)NASS * FMOE];       // 64 MB
__device__ float g_part[(size_t)NASS * HDIM];      // 128 MB
__device__ float g_shact[(size_t)T_TOK * FSH];     // 32 MB

// ---------------------------------------------------------------------------
// Packed f32x2 helpers (Blackwell FFMA2 — only reachable via PTX)
// ---------------------------------------------------------------------------
__device__ __forceinline__ unsigned long long pack2(float lo, float hi) {
    unsigned long long r;
    asm("mov.b64 %0, {%1, %2};" : "=l"(r) : "f"(lo), "f"(hi));
    return r;
}
__device__ __forceinline__ void unpack2(unsigned long long v, float& lo, float& hi) {
    asm("mov.b64 {%0, %1}, %2;" : "=f"(lo), "=f"(hi) : "l"(v));
}
__device__ __forceinline__ unsigned long long ffma2(unsigned long long a,
                                                    unsigned long long b,
                                                    unsigned long long c) {
    unsigned long long d;
    asm("fma.rn.f32x2 %0, %1, %2, %3;" : "=l"(d) : "l"(a), "l"(b), "l"(c));
    return d;
}

__device__ __forceinline__ float silu(float x) {
    return x / (1.f + expf(-x));
}

// ---------------------------------------------------------------------------
// 0) zero the per-launch counters (graph replays must be idempotent)
// ---------------------------------------------------------------------------
__global__ void zero_kernel() {
    int i = threadIdx.x;
    if (i < NEXP) { g_counts[i] = 0; g_fill[i] = 0; }
}

// ---------------------------------------------------------------------------
// 1) Router: logits, sigmoid, grouped top-2-sum, top-2 groups, top-4 experts
//    Faithful to jax.lax.top_k tie-breaking (lowest index wins on ties).
// ---------------------------------------------------------------------------
__global__ void router_kernel(const float* __restrict__ hidden,
                              const float* __restrict__ gw,
                              const float* __restrict__ bias) {
    int t    = blockIdx.x;
    int lane = threadIdx.x & 31;
    int wid  = threadIdx.x >> 5;   // expert id, 16 warps
    __shared__ float slog[NEXP];

    const float* hrow = hidden + (size_t)t * HDIM;
    const float* wrow = gw + (size_t)wid * HDIM;
    float s = 0.f;
    for (int h = lane; h < HDIM; h += 32) s += hrow[h] * wrow[h];
#pragma unroll
    for (int o = 16; o > 0; o >>= 1) s += __shfl_down_sync(0xffffffffu, s, o);
    if (lane == 0) slog[wid] = s;
    __syncthreads();

    if (threadIdx.x == 0) {
        float sc[NEXP], s4c[NEXP];
#pragma unroll
        for (int e = 0; e < NEXP; e++) {
            float sg = 1.f / (1.f + expf(-slog[e]));
            sc[e]  = sg;
            s4c[e] = sg + bias[e];
        }
        // group scores: sum of top-2 within each group of 4
        float gsc[NGRP];
#pragma unroll
        for (int g = 0; g < NGRP; g++) {
            int i1 = 0; float v1 = -INFINITY;
            for (int j = 0; j < EPG; j++) {
                float v = s4c[g * EPG + j];
                if (v > v1) { v1 = v; i1 = j; }
            }
            float v2 = -INFINITY;
            for (int j = 0; j < EPG; j++) {
                if (j == i1) continue;
                float v = s4c[g * EPG + j];
                if (v > v2) v2 = v;
            }
            gsc[g] = v1 + v2;
        }
        // top-2 groups
        int g0 = 0; float gv0 = -INFINITY;
        for (int g = 0; g < NGRP; g++) if (gsc[g] > gv0) { gv0 = gsc[g]; g0 = g; }
        int g1 = -1; float gv1 = -INFINITY;
        for (int g = 0; g < NGRP; g++) {
            if (g == g0) continue;
            if (gsc[g] > gv1) { gv1 = gsc[g]; g1 = g; }
        }
        float masked[NEXP];
#pragma unroll
        for (int e = 0; e < NEXP; e++) {
            int g = e / EPG;
            masked[e] = (g == g0 || g == g1) ? s4c[e] : -INFINITY;
        }
        int   idx[TOPK];
        float wraw[TOPK];
        float wsum = 0.f;
#pragma unroll
        for (int k = 0; k < TOPK; k++) {
            int best = 0; float bv = -INFINITY;
            for (int e = 0; e < NEXP; e++)
                if (masked[e] > bv) { bv = masked[e]; best = e; }
            masked[best] = -INFINITY;
            idx[k]  = best;
            wraw[k] = sc[best];        // raw sigmoid scores (no bias)
            wsum   += sc[best];
        }
        float inv = RSCALE / (wsum + 1e-20f);
#pragma unroll
        for (int k = 0; k < TOPK; k++) {
            g_topk_idx[t * TOPK + k] = idx[k];
            g_topk_w[t * TOPK + k]   = wraw[k] * inv;
            atomicAdd(&g_counts[idx[k]], 1);
        }
    }
}

// ---------------------------------------------------------------------------
// 2) exclusive scan over 16 expert counts
// ---------------------------------------------------------------------------
__global__ void offsets_kernel() {
    if (threadIdx.x == 0) {
        int acc = 0;
        for (int e = 0; e < NEXP; e++) { g_offsets[e] = acc; acc += g_counts[e]; }
        g_offsets[NEXP] = acc;   // == NASS
    }
}

// ---------------------------------------------------------------------------
// 3) dispatch: build per-expert contiguous assignment lists
//    (order within a segment is nondeterministic, but every result is keyed
//     by the (t,k) slot, so the final output is deterministic)
// ---------------------------------------------------------------------------
__global__ void dispatch_kernel() {
    int t = blockIdx.x * blockDim.x + threadIdx.x;
    if (t >= T_TOK) return;
#pragma unroll
    for (int k = 0; k < TOPK; k++) {
        int e    = g_topk_idx[t * TOPK + k];
        int pos  = atomicAdd(&g_fill[e], 1);
        int slot = g_offsets[e] + pos;
        g_tk[slot] = t * TOPK + k;
        g_w[slot]  = g_topk_w[t * TOPK + k];
    }
}

// ---------------------------------------------------------------------------
// 4) Fused gate+up GEMM with SiLU epilogue.
//    GATHER=true : routed experts, A rows gathered via token list, 64x64 tiles
//                  over [n_e, FMOE] per expert, K = HDIM.
//    GATHER=false: shared expert, A = hidden directly, out = g_shact, F = FSH.
// ---------------------------------------------------------------------------
template <bool GATHER>
__global__ __launch_bounds__(256)
void gateup_kernel(const float* __restrict__ A,
                   const float* __restrict__ Wg,
                   const float* __restrict__ Wu) {
    constexpr int BM = 64, BN = 64, BK = 16, LDS_ = BM + 4;
    constexpr int F = GATHER ? FMOE : FSH;
    constexpr int K = HDIM;
    __shared__ float As[BK][LDS_];
    __shared__ float Bgs[BK][LDS_];
    __shared__ float Bus[BK][LDS_];

    int e = GATHER ? blockIdx.z : 0;
    int seg, nrows;
    if (GATHER) { seg = g_offsets[e]; nrows = g_offsets[e + 1] - seg; }
    else        { seg = 0;            nrows = T_TOK; }

    int m0 = blockIdx.y * BM;
    if (m0 >= nrows) return;
    int n0 = blockIdx.x * BN;

    const float* wg = Wg + (size_t)e * F * K;
    const float* wu = Wu + (size_t)e * F * K;
    float* Out = GATHER ? g_act : g_shact;

    int tid = threadIdx.x;
    int row = tid >> 2;            // 0..63
    int kq  = (tid & 3) * 4;       // 0,4,8,12

    bool avalid = (m0 + row) < nrows;
    const float* arow = A;
    if (avalid) {
        size_t r = GATHER ? (size_t)(g_tk[seg + m0 + row] >> 2)
                          : (size_t)(m0 + row);
        arow = A + r * (size_t)K;
    }
    const float* bgrow = wg + (size_t)(n0 + row) * K;
    const float* burow = wu + (size_t)(n0 + row) * K;

    int tx = tid & 15, ty = tid >> 4;
    unsigned long long accg[4][2], accu[4][2];
#pragma unroll
    for (int i = 0; i < 4; i++) {
        accg[i][0] = accg[i][1] = 0ull;
        accu[i][0] = accu[i][1] = 0ull;
    }

    for (int k0 = 0; k0 < K; k0 += BK) {
        float4 av = avalid ? *(const float4*)(arow + k0 + kq)
                           : make_float4(0.f, 0.f, 0.f, 0.f);
        float4 bg = *(const float4*)(bgrow + k0 + kq);
        float4 bu = *(const float4*)(burow + k0 + kq);
        As[kq + 0][row] = av.x; As[kq + 1][row] = av.y;
        As[kq + 2][row] = av.z; As[kq + 3][row] = av.w;
        Bgs[kq + 0][row] = bg.x; Bgs[kq + 1][row] = bg.y;
        Bgs[kq + 2][row] = bg.z; Bgs[kq + 3][row] = bg.w;
        Bus[kq + 0][row] = bu.x; Bus[kq + 1][row] = bu.y;
        Bus[kq + 2][row] = bu.z; Bus[kq + 3][row] = bu.w;
        __syncthreads();
#pragma unroll
        for (int kk = 0; kk < BK; kk++) {
            const float4 a4 = *(const float4*)&As[kk][ty * 4];
            unsigned long long a2[4] = { pack2(a4.x, a4.x), pack2(a4.y, a4.y),
                                         pack2(a4.z, a4.z), pack2(a4.w, a4.w) };
            const ulonglong2 bg2 = *(const ulonglong2*)&Bgs[kk][tx * 4];
            const ulonglong2 bu2 = *(const ulonglong2*)&Bus[kk][tx * 4];
#pragma unroll
            for (int i = 0; i < 4; i++) {
                accg[i][0] = ffma2(a2[i], bg2.x, accg[i][0]);
                accg[i][1] = ffma2(a2[i], bg2.y, accg[i][1]);
                accu[i][0] = ffma2(a2[i], bu2.x, accu[i][0]);
                accu[i][1] = ffma2(a2[i], bu2.y, accu[i][1]);
            }
        }
        __syncthreads();
    }

#pragma unroll
    for (int i = 0; i < 4; i++) {
        int m = m0 + ty * 4 + i;
        if (m >= nrows) continue;
        float gg0, gg1, gg2, gg3, uu0, uu1, uu2, uu3;
        unpack2(accg[i][0], gg0, gg1); unpack2(accg[i][1], gg2, gg3);
        unpack2(accu[i][0], uu0, uu1); unpack2(accu[i][1], uu2, uu3);
        float4 o;
        o.x = silu(gg0) * uu0;
        o.y = silu(gg1) * uu1;
        o.z = silu(gg2) * uu2;
        o.w = silu(gg3) * uu3;
        *(float4*)&Out[(size_t)(seg + m) * F + n0 + tx * 4] = o;
    }
}

// ---------------------------------------------------------------------------
// 5) Down projection GEMM.
//    ROUTED=true : A = g_act (slot rows), scaled by routing weight, scattered
//                  to g_part[(t*4+k)][H]. K = FMOE.
//    ROUTED=false: A = g_shact, plain store into d_out. K = FSH.
// ---------------------------------------------------------------------------
template <bool ROUTED>
__global__ __launch_bounds__(256)
void down_kernel(const float* __restrict__ W, float* __restrict__ OutDense) {
    constexpr int BM = 64, BN = 64, BK = 16, LDS_ = BM + 4;
    constexpr int K = ROUTED ? FMOE : FSH;
    constexpr int N = HDIM;
    __shared__ float As[BK][LDS_];
    __shared__ float Bs[BK][LDS_];

    int e = ROUTED ? blockIdx.z : 0;
    int seg, nrows;
    if (ROUTED) { seg = g_offsets[e]; nrows = g_offsets[e + 1] - seg; }
    else        { seg = 0;            nrows = T_TOK; }

    int m0 = blockIdx.y * BM;
    if (m0 >= nrows) return;
    int n0 = blockIdx.x * BN;

    const float* A = ROUTED ? g_act : g_shact;
    const float* we = W + (size_t)e * N * K;

    int tid = threadIdx.x;
    int row = tid >> 2;
    int kq  = (tid & 3) * 4;

    bool avalid = (m0 + row) < nrows;
    const float* arow = A + (size_t)(seg + m0 + row) * K;
    const float* brow = we + (size_t)(n0 + row) * K;

    int tx = tid & 15, ty = tid >> 4;
    unsigned long long acc[4][2];
#pragma unroll
    for (int i = 0; i < 4; i++) acc[i][0] = acc[i][1] = 0ull;

    for (int k0 = 0; k0 < K; k0 += BK) {
        float4 av = avalid ? *(const float4*)(arow + k0 + kq)
                           : make_float4(0.f, 0.f, 0.f, 0.f);
        float4 bv = *(const float4*)(brow + k0 + kq);
        As[kq + 0][row] = av.x; As[kq + 1][row] = av.y;
        As[kq + 2][row] = av.z; As[kq + 3][row] = av.w;
        Bs[kq + 0][row] = bv.x; Bs[kq + 1][row] = bv.y;
        Bs[kq + 2][row] = bv.z; Bs[kq + 3][row] = bv.w;
        __syncthreads();
#pragma unroll
        for (int kk = 0; kk < BK; kk++) {
            const float4 a4 = *(const float4*)&As[kk][ty * 4];
            unsigned long long a2[4] = { pack2(a4.x, a4.x), pack2(a4.y, a4.y),
                                         pack2(a4.z, a4.z), pack2(a4.w, a4.w) };
            const ulonglong2 b2 = *(const ulonglong2*)&Bs[kk][tx * 4];
#pragma unroll
            for (int i = 0; i < 4; i++) {
                acc[i][0] = ffma2(a2[i], b2.x, acc[i][0]);
                acc[i][1] = ffma2(a2[i], b2.y, acc[i][1]);
            }
        }
        __syncthreads();
    }

#pragma unroll
    for (int i = 0; i < 4; i++) {
        int m = m0 + ty * 4 + i;
        if (m >= nrows) continue;
        float c0, c1, c2, c3;
        unpack2(acc[i][0], c0, c1);
        unpack2(acc[i][1], c2, c3);
        if (ROUTED) {
            int slot = seg + m;
            int tk   = g_tk[slot];
            float ws = g_w[slot];
            float4 o = make_float4(c0 * ws, c1 * ws, c2 * ws, c3 * ws);
            *(float4*)&g_part[(size_t)tk * HDIM + n0 + tx * 4] = o;
        } else {
            float4 o = make_float4(c0, c1, c2, c3);
            *(float4*)&OutDense[(size_t)m * HDIM + n0 + tx * 4] = o;
        }
    }
}

// ---------------------------------------------------------------------------
// 6) combine: out[t][h] = shared_down (already in d_out) + sum_k part[t,k][h]
// ---------------------------------------------------------------------------
__global__ void combine_kernel(float* __restrict__ out) {
    size_t i = (size_t)blockIdx.x * blockDim.x + threadIdx.x;  // float4 index
    size_t v = i * 4;
    int t = (int)(v / HDIM);
    int h = (int)(v % HDIM);
    float4 o = *(float4*)&out[v];
#pragma unroll
    for (int k = 0; k < TOPK; k++) {
        const float4 p = *(const float4*)&g_part[(size_t)(t * TOPK + k) * HDIM + h];
        o.x += p.x; o.y += p.y; o.z += p.z; o.w += p.w;
    }
    *(float4*)&out[v] = o;
}

// ---------------------------------------------------------------------------
// launch
// ---------------------------------------------------------------------------
extern "C" void kernel_launch(void* const* d_in, const int* in_sizes, int n_in,
                              void* d_out, int out_size) {
    const float* hidden      = (const float*)d_in[0];
    const float* gate_weight = (const float*)d_in[1];
    const float* bias        = (const float*)d_in[2];
    const float* gate_w      = (const float*)d_in[3];
    const float* up_w        = (const float*)d_in[4];
    const float* down_w      = (const float*)d_in[5];
    const float* sh_gate_w   = (const float*)d_in[6];
    const float* sh_up_w     = (const float*)d_in[7];
    const float* sh_down_w   = (const float*)d_in[8];
    float* out = (float*)d_out;

    zero_kernel<<<1, 32>>>();
    router_kernel<<<T_TOK, 512>>>(hidden, gate_weight, bias);
    offsets_kernel<<<1, 1>>>();
    dispatch_kernel<<<(T_TOK + 255) / 256, 256>>>();

    // routed experts
    gateup_kernel<true><<<dim3(FMOE / 64, T_TOK / 64, NEXP), 256>>>(hidden, gate_w, up_w);
    down_kernel<true><<<dim3(HDIM / 64, T_TOK / 64, NEXP), 256>>>(down_w, nullptr);

    // shared expert
    gateup_kernel<false><<<dim3(FSH / 64, T_TOK / 64, 1), 256>>>(hidden, sh_gate_w, sh_up_w);
    down_kernel<false><<<dim3(HDIM / 64, T_TOK / 64, 1), 256>>>(sh_down_w, out);

    // final sum
    combine_kernel<<<(T_TOK * HDIM / 4) / 256, 256>>>(out);
}

// round 6
// speedup vs baseline: 2.4121x; 2.4121x over previous
#include <cuda_runtime.h>
#include <cuda_bf16.h>
#include <math.h>
#include <stdint.h>

// ---------------------------------------------------------------------------
// Arch-feature gate: tcgen05 only compiles in arch/family-specific passes.
// Generic sm_103 pass gets an mma.sync fallback (legal since sm_80).
// ---------------------------------------------------------------------------
#if defined(__CUDA_ARCH__) && (__CUDA_ARCH__ >= 1000) && \
    (defined(__CUDA_ARCH_FEAT_SM103_ALL) || defined(__CUDA_ARCH_FEAT_SM100_ALL) || \
     defined(__CUDA_ARCH_SPECIFIC__) || defined(__CUDA_ARCH_FAMILY_SPECIFIC__))
#define USE_TC 1
#else
#define USE_TC 0
#endif

// ---------------------------------------------------------------------------
// Problem constants
// ---------------------------------------------------------------------------
constexpr int T_TOK = 4096;
constexpr int HDIM  = 2048;
constexpr int FMOE  = 1024;
constexpr int FSH   = 2048;
constexpr int NEXP  = 16;
constexpr int TOPK  = 4;
constexpr int NGRP  = 4;
constexpr int EPG   = NEXP / NGRP;
constexpr int NASS  = T_TOK * TOPK;
constexpr float RSCALE = 2.5f;

// ---------------------------------------------------------------------------
// Scratch layout
// ---------------------------------------------------------------------------
constexpr size_t SZ_RW  = (size_t)NEXP * FMOE * HDIM * 2;
constexpr size_t SZ_DW  = (size_t)NEXP * HDIM * FMOE * 2;
constexpr size_t SZ_SW  = (size_t)FSH * HDIM * 2;
constexpr size_t SZ_HID = (size_t)T_TOK * HDIM * 2;
constexpr size_t SZ_GU  = (size_t)NASS * FMOE * 4;
constexpr size_t SZ_ACT = (size_t)NASS * FMOE * 2;
constexpr size_t SZ_SHB = (size_t)T_TOK * FSH * 4;
constexpr size_t SZ_SHA = (size_t)T_TOK * FSH * 2;
constexpr size_t SZ_PART= (size_t)NASS * HDIM * 4;

constexpr size_t O_WG_HI  = 0;
constexpr size_t O_WG_LO  = O_WG_HI  + SZ_RW;
constexpr size_t O_WU_HI  = O_WG_LO  + SZ_RW;
constexpr size_t O_WU_LO  = O_WU_HI  + SZ_RW;
constexpr size_t O_WD_HI  = O_WU_LO  + SZ_RW;
constexpr size_t O_WD_LO  = O_WD_HI  + SZ_DW;
constexpr size_t O_WSG_HI = O_WD_LO  + SZ_DW;
constexpr size_t O_WSG_LO = O_WSG_HI + SZ_SW;
constexpr size_t O_WSU_HI = O_WSG_LO + SZ_SW;
constexpr size_t O_WSU_LO = O_WSU_HI + SZ_SW;
constexpr size_t O_WSD_HI = O_WSU_LO + SZ_SW;
constexpr size_t O_WSD_LO = O_WSD_HI + SZ_SW;
constexpr size_t O_HID_HI = O_WSD_LO + SZ_SW;
constexpr size_t O_HID_LO = O_HID_HI + SZ_HID;
constexpr size_t O_GBUF   = O_HID_LO + SZ_HID;
constexpr size_t O_UBUF   = O_GBUF   + SZ_GU;
constexpr size_t O_ACT_HI = O_UBUF   + SZ_GU;
constexpr size_t O_ACT_LO = O_ACT_HI + SZ_ACT;
constexpr size_t O_SHG    = O_ACT_LO + SZ_ACT;
constexpr size_t O_SHU    = O_SHG    + SZ_SHB;
constexpr size_t O_SHA_HI = O_SHU    + SZ_SHB;
constexpr size_t O_SHA_LO = O_SHA_HI + SZ_SHA;
constexpr size_t O_PART   = O_SHA_LO + SZ_SHA;
constexpr size_t O_TOTAL  = O_PART   + SZ_PART;

__device__ __align__(256) char g_scratch[O_TOTAL];

__device__ int   g_counts[NEXP];
__device__ int   g_fill[NEXP];
__device__ int   g_offsets[NEXP + 1];
__device__ int   g_topk_idx[NASS];
__device__ float g_topk_w[NASS];
__device__ int   g_tk[NASS];
__device__ float g_w[NASS];

// ---------------------------------------------------------------------------
// Generic helpers
// ---------------------------------------------------------------------------
__device__ __forceinline__ uint32_t smem_to_u32(const void* p) {
    uint32_t a;
    asm("{ .reg .u64 t; cvta.to.shared.u64 t, %1; cvt.u32.u64 %0, t; }"
        : "=r"(a) : "l"(p));
    return a;
}
__device__ __forceinline__ uint32_t swz32(uint32_t x) {
    return x ^ ((x >> 3) & 0x70u);
}
__device__ __forceinline__ float silu(float x) { return x / (1.f + expf(-x)); }

// ---- fallback-path helpers (legal on generic sm_103 target) ----
__device__ __forceinline__ void cp16(uint32_t dst, const void* src) {
    asm volatile("cp.async.cg.shared.global [%0], [%1], 16;" :: "r"(dst), "l"(src));
}
__device__ __forceinline__ void ldsm_x4(uint32_t* r, uint32_t addr) {
    asm volatile("ldmatrix.sync.aligned.m8n8.x4.shared.b16 {%0,%1,%2,%3}, [%4];"
        : "=r"(r[0]), "=r"(r[1]), "=r"(r[2]), "=r"(r[3]) : "r"(addr));
}
__device__ __forceinline__ void mma_bf16(float* c, const uint32_t* a, const uint32_t* b) {
    asm volatile(
        "mma.sync.aligned.m16n8k16.row.col.f32.bf16.bf16.f32 "
        "{%0,%1,%2,%3}, {%4,%5,%6,%7}, {%8,%9}, {%0,%1,%2,%3};"
        : "+f"(c[0]), "+f"(c[1]), "+f"(c[2]), "+f"(c[3])
        : "r"(a[0]), "r"(a[1]), "r"(a[2]), "r"(a[3]), "r"(b[0]), "r"(b[1]));
}

// ---- tcgen05-path helpers (only in arch-specific passes) ----
#if USE_TC
__device__ __forceinline__ uint32_t elect_one_pred() {
    uint32_t pred;
    asm volatile(
        "{\n\t.reg .pred p;\n\t"
        "elect.sync _|p, 0xFFFFFFFF;\n\t"
        "selp.b32 %0, 1, 0, p;\n\t}"
        : "=r"(pred));
    return pred;
}
#define MBARRIER_INIT(addr, cnt) \
    asm volatile("mbarrier.init.shared.b64 [%0], %1;" :: "r"((uint32_t)(addr)), "r"((uint32_t)(cnt)) : "memory")
#define MBARRIER_INVAL(addr) \
    asm volatile("mbarrier.inval.shared.b64 [%0];" :: "r"((uint32_t)(addr)) : "memory")

__device__ __forceinline__ void mbar_wait(uint32_t addr, int parity) {
    uint32_t done;
    asm volatile(
        "{\n\t.reg .pred p;\n\t"
        "mbarrier.try_wait.parity.acquire.cta.shared::cta.b64 p, [%1], %2;\n\t"
        "selp.b32 %0, 1, 0, p;\n\t}"
        : "=r"(done) : "r"(addr), "r"((uint32_t)parity) : "memory");
    while (!done) {
        asm volatile(
            "{\n\t.reg .pred p;\n\t"
            "mbarrier.try_wait.parity.acquire.cta.shared::cta.b64 p, [%1], %2, 0x989680;\n\t"
            "selp.b32 %0, 1, 0, p;\n\t}"
            : "=r"(done) : "r"(addr), "r"((uint32_t)parity) : "memory");
    }
}

#define TCGEN05_ALLOC(smem_addr, nCols) \
    asm volatile("tcgen05.alloc.cta_group::1.sync.aligned.shared::cta.b32 [%0], %1;" \
        :: "r"((uint32_t)(smem_addr)), "r"((uint32_t)(nCols)) : "memory")
#define TCGEN05_DEALLOC(tmem, nCols) \
    asm volatile("tcgen05.dealloc.cta_group::1.sync.aligned.b32 %0, %1;" :: "r"(tmem), "r"((uint32_t)(nCols)))
#define TCGEN05_RELINQ() \
    asm volatile("tcgen05.relinquish_alloc_permit.cta_group::1.sync.aligned;")
#define TCGEN05_COMMIT(mbar) \
    asm volatile("tcgen05.commit.cta_group::1.mbarrier::arrive::one.shared::cluster.b64 [%0];" \
        :: "r"((uint32_t)(mbar)) : "memory")
#define TCGEN05_FENCE_AFTER() asm volatile("tcgen05.fence::after_thread_sync;" ::: "memory")
#define TCGEN05_WAIT_LD() asm volatile("tcgen05.wait::ld.sync.aligned;" ::: "memory")
#define FENCE_PROXY_ASYNC() asm volatile("fence.proxy.async.shared::cta;" ::: "memory")

#define TCGEN05_LD_32X32B_X32(r, tmem_addr) \
    asm volatile( \
        "tcgen05.ld.sync.aligned.32x32b.x32.b32 " \
        "{%0, %1, %2, %3, %4, %5, %6, %7, " \
        " %8, %9, %10, %11, %12, %13, %14, %15, " \
        " %16, %17, %18, %19, %20, %21, %22, %23, " \
        " %24, %25, %26, %27, %28, %29, %30, %31}, [%32];" \
        : "=r"((r)[0]),  "=r"((r)[1]),  "=r"((r)[2]),  "=r"((r)[3]), \
          "=r"((r)[4]),  "=r"((r)[5]),  "=r"((r)[6]),  "=r"((r)[7]), \
          "=r"((r)[8]),  "=r"((r)[9]),  "=r"((r)[10]), "=r"((r)[11]), \
          "=r"((r)[12]), "=r"((r)[13]), "=r"((r)[14]), "=r"((r)[15]), \
          "=r"((r)[16]), "=r"((r)[17]), "=r"((r)[18]), "=r"((r)[19]), \
          "=r"((r)[20]), "=r"((r)[21]), "=r"((r)[22]), "=r"((r)[23]), \
          "=r"((r)[24]), "=r"((r)[25]), "=r"((r)[26]), "=r"((r)[27]), \
          "=r"((r)[28]), "=r"((r)[29]), "=r"((r)[30]), "=r"((r)[31]) \
        : "r"(tmem_addr))

static constexpr uint64_t SMEM_DESC_BASE_SW128 =
    (uint64_t(2)  << 61) | (uint64_t(1) << 46) | (uint64_t(64) << 32) | (uint64_t(1) << 16);
#define MAKE_SMEM_DESC(base_addr) \
    (SMEM_DESC_BASE_SW128 | ((uint64_t)((base_addr) >> 4) & 0x3FFF))

// idesc: F32 accum, BF16 A/B, N=128, M=128  (verified vs example 0x8080490)
constexpr uint32_t IDESC_128x128 = (1u<<4) | (1u<<7) | (1u<<10) | (16u<<17) | (8u<<24);

__device__ __forceinline__ void mma_f16_ss(uint32_t d, uint64_t a, uint64_t b,
                                           uint32_t idesc, bool acc) {
    uint32_t en = acc ? 1u : 0u;
    asm volatile(
        "{\n\t.reg .pred p;\n\t"
        "setp.ne.u32 p, %4, 0;\n\t"
        "tcgen05.mma.cta_group::1.kind::f16 [%0], %1, %2, %3, {%5, %5, %5, %5}, p;\n\t}"
        :: "r"(d), "l"(a), "l"(b), "r"(idesc), "r"(en), "r"(0u) : "memory");
}
#endif  // USE_TC

// ---------------------------------------------------------------------------
// 0) zero counters
// ---------------------------------------------------------------------------
__global__ void zero_kernel() {
    int i = threadIdx.x;
    if (i < NEXP) { g_counts[i] = 0; g_fill[i] = 0; }
}

// ---------------------------------------------------------------------------
// 1) Router (validated in R4)
// ---------------------------------------------------------------------------
__global__ void router_kernel(const float* __restrict__ hidden,
                              const float* __restrict__ gw,
                              const float* __restrict__ bias) {
    int t    = blockIdx.x;
    int lane = threadIdx.x & 31;
    int wid  = threadIdx.x >> 5;
    __shared__ float slog[NEXP];

    const float* hrow = hidden + (size_t)t * HDIM;
    const float* wrow = gw + (size_t)wid * HDIM;
    float s = 0.f;
    for (int h = lane; h < HDIM; h += 32) s += hrow[h] * wrow[h];
#pragma unroll
    for (int o = 16; o > 0; o >>= 1) s += __shfl_down_sync(0xffffffffu, s, o);
    if (lane == 0) slog[wid] = s;
    __syncthreads();

    if (threadIdx.x == 0) {
        float sc[NEXP], s4c[NEXP];
#pragma unroll
        for (int e = 0; e < NEXP; e++) {
            float sg = 1.f / (1.f + expf(-slog[e]));
            sc[e] = sg; s4c[e] = sg + bias[e];
        }
        float gsc[NGRP];
#pragma unroll
        for (int g = 0; g < NGRP; g++) {
            int i1 = 0; float v1 = -INFINITY;
            for (int j = 0; j < EPG; j++) {
                float v = s4c[g * EPG + j];
                if (v > v1) { v1 = v; i1 = j; }
            }
            float v2 = -INFINITY;
            for (int j = 0; j < EPG; j++) {
                if (j == i1) continue;
                float v = s4c[g * EPG + j];
                if (v > v2) v2 = v;
            }
            gsc[g] = v1 + v2;
        }
        int g0 = 0; float gv0 = -INFINITY;
        for (int g = 0; g < NGRP; g++) if (gsc[g] > gv0) { gv0 = gsc[g]; g0 = g; }
        int g1 = -1; float gv1 = -INFINITY;
        for (int g = 0; g < NGRP; g++) {
            if (g == g0) continue;
            if (gsc[g] > gv1) { gv1 = gsc[g]; g1 = g; }
        }
        float masked[NEXP];
#pragma unroll
        for (int e = 0; e < NEXP; e++) {
            int g = e / EPG;
            masked[e] = (g == g0 || g == g1) ? s4c[e] : -INFINITY;
        }
        int idx[TOPK]; float wraw[TOPK]; float wsum = 0.f;
#pragma unroll
        for (int k = 0; k < TOPK; k++) {
            int best = 0; float bv = -INFINITY;
            for (int e = 0; e < NEXP; e++)
                if (masked[e] > bv) { bv = masked[e]; best = e; }
            masked[best] = -INFINITY;
            idx[k] = best; wraw[k] = sc[best]; wsum += sc[best];
        }
        float inv = RSCALE / (wsum + 1e-20f);
#pragma unroll
        for (int k = 0; k < TOPK; k++) {
            g_topk_idx[t * TOPK + k] = idx[k];
            g_topk_w[t * TOPK + k]   = wraw[k] * inv;
            atomicAdd(&g_counts[idx[k]], 1);
        }
    }
}

__global__ void offsets_kernel() {
    if (threadIdx.x == 0) {
        int acc = 0;
        for (int e = 0; e < NEXP; e++) { g_offsets[e] = acc; acc += g_counts[e]; }
        g_offsets[NEXP] = acc;
    }
}

__global__ void dispatch_kernel() {
    int t = blockIdx.x * blockDim.x + threadIdx.x;
    if (t >= T_TOK) return;
#pragma unroll
    for (int k = 0; k < TOPK; k++) {
        int e    = g_topk_idx[t * TOPK + k];
        int pos  = atomicAdd(&g_fill[e], 1);
        int slot = g_offsets[e] + pos;
        g_tk[slot] = t * TOPK + k;
        g_w[slot]  = g_topk_w[t * TOPK + k];
    }
}

// ---------------------------------------------------------------------------
// split helpers: x = hi(bf16) + lo(bf16)
// ---------------------------------------------------------------------------
__device__ __forceinline__ void split_pair(float a0, float a1,
                                           __nv_bfloat162& hp, __nv_bfloat162& lp) {
    hp = __floats2bfloat162_rn(a0, a1);
    float l0 = a0 - __bfloat162float(__low2bfloat16(hp));
    float l1 = a1 - __bfloat162float(__high2bfloat16(hp));
    lp = __floats2bfloat162_rn(l0, l1);
}

// ---------------------------------------------------------------------------
// prep: weights -> tile-ordered, SW128-preswizzled bf16 hi/lo images
// ---------------------------------------------------------------------------
template <int F, int K>
__global__ void prep_weight(const float* __restrict__ src,
                            size_t hi_off, size_t lo_off, int npairs) {
    int i = blockIdx.x * blockDim.x + threadIdx.x;
    if (i >= npairs) return;
    size_t elem = (size_t)i * 2;
    int k = (int)(elem % K);
    int f = (int)((elem / K) % F);
    int e = (int)(elem / ((size_t)K * F));
    float2 v = *(const float2*)(src + elem);
    __nv_bfloat162 hp, lp;
    split_pair(v.x, v.y, hp, lp);
    int n = f >> 7, r = f & 127, c = k >> 6, col = k & 63;
    size_t tb = ((size_t)(e * (F >> 7) + n) * (K >> 6) + c) * 16384;
    int off = r * 128 + col * 2;
    int sw = off ^ ((off >> 3) & 0x70);
    *(__nv_bfloat162*)(g_scratch + hi_off + tb + sw) = hp;
    *(__nv_bfloat162*)(g_scratch + lo_off + tb + sw) = lp;
}

__global__ void prep_split(const float* __restrict__ src,
                           size_t hi_off, size_t lo_off, int npairs) {
    int i = blockIdx.x * blockDim.x + threadIdx.x;
    if (i >= npairs) return;
    float2 v = *(const float2*)(src + (size_t)i * 2);
    __nv_bfloat162 hp, lp;
    split_pair(v.x, v.y, hp, lp);
    ((__nv_bfloat162*)(g_scratch + hi_off))[i] = hp;
    ((__nv_bfloat162*)(g_scratch + lo_off))[i] = lp;
}

__global__ void act_kernel(size_t g_off, size_t u_off,
                           size_t hi_off, size_t lo_off, int npairs) {
    int i = blockIdx.x * blockDim.x + threadIdx.x;
    if (i >= npairs) return;
    float2 g2 = ((const float2*)(g_scratch + g_off))[i];
    float2 u2 = ((const float2*)(g_scratch + u_off))[i];
    float a0 = silu(g2.x) * u2.x;
    float a1 = silu(g2.y) * u2.y;
    __nv_bfloat162 hp, lp;
    split_pair(a0, a1, hp, lp);
    ((__nv_bfloat162*)(g_scratch + hi_off))[i] = hp;
    ((__nv_bfloat162*)(g_scratch + lo_off))[i] = lp;
}

// ---------------------------------------------------------------------------
// Grouped GEMM, 128x128 CTA tile, K-chunk 64, split-bf16 (3 MMA terms).
// tcgen05 path in arch-specific passes; mma.sync fallback otherwise.
// AMODE: 0 plain rows, 1 gather hidden rows via g_tk, 2 slot rows.
// EMODE: 0 plain store, 1 scale by g_w + scatter to g_part[tk].
// ---------------------------------------------------------------------------
constexpr int GSMEM_BYTES = 1024 + 2 * 65536;

template <int KD, int ND, int AMODE, int EMODE>
__global__ void __launch_bounds__(256)
mma_gemm(size_t a_hi_off, size_t a_lo_off,
         size_t w_hi_off, size_t w_lo_off,
         size_t out_off, float* ext_out) {
    constexpr int KC = KD / 64;
    constexpr int NT = ND / 128;
    extern __shared__ char smem[];
    uint32_t sb = smem_to_u32(smem);

    int e, seg, nrows;
    if (AMODE == 0) { e = 0; seg = 0; nrows = T_TOK; }
    else { e = blockIdx.z; seg = g_offsets[e]; nrows = g_offsets[e + 1] - seg; }
    int m0 = blockIdx.y * 128;
    if (m0 >= nrows) return;
    int nb = blockIdx.x;

    int tid = threadIdx.x, wid = tid >> 5, lid = tid & 31;

    // ---- A staging addressing: thread = (row, half of 128B row) ----
    const __nv_bfloat16* a_hi = (const __nv_bfloat16*)(g_scratch + a_hi_off);
    const __nv_bfloat16* a_lo = (const __nv_bfloat16*)(g_scratch + a_lo_off);
    int r = tid >> 1, half = tid & 1;
    int mrow = m0 + r;
    bool av = mrow < nrows;
    size_t arow;
    if (AMODE == 1)      arow = (size_t)(g_tk[seg + (av ? mrow : m0)] >> 2);
    else if (AMODE == 2) arow = (size_t)(seg + (av ? mrow : m0));
    else                 arow = (size_t)(av ? mrow : m0);
    const char* ah0 = (const char*)(a_hi + arow * KD + half * 32);
    const char* al0 = (const char*)(a_lo + arow * KD + half * 32);
    uint32_t asw[4];
#pragma unroll
    for (int u = 0; u < 4; u++)
        asw[u] = swz32((uint32_t)(r * 128 + half * 64 + u * 16));

    // ---- B: preswizzled 16KB tiles, identity copy ----
    size_t wtile = (size_t)(e * NT + nb) * KC;
    const char* bh0 = g_scratch + w_hi_off + wtile * 16384 + tid * 64;
    const char* bl0 = g_scratch + w_lo_off + wtile * 16384 + tid * 64;

#if USE_TC
    // =======================================================================
    // tcgen05 path
    // =======================================================================
    if (wid == 0) TCGEN05_ALLOC(sb, 128);
    if (tid == 0) { MBARRIER_INIT(sb + 8, 1); MBARRIER_INIT(sb + 16, 1); }
    __syncthreads();
    uint32_t tmem;
    asm volatile("ld.shared.b32 %0, [%1];" : "=r"(tmem) : "r"(sb));
    if (wid == 0) TCGEN05_RELINQ();

    int ph[2] = {0, 0};
    for (int c = 0; c < KC; c++) {
        int s = c & 1;
        char* Ah = smem + 1024 + s * 65536;
        if (c >= 2) { mbar_wait(sb + 8 + s * 8, ph[s]); ph[s] ^= 1; }
        const char* ah = ah0 + (size_t)c * 128;
        const char* al = al0 + (size_t)c * 128;
        const char* bh = bh0 + (size_t)c * 16384;
        const char* bl = bl0 + (size_t)c * 16384;
#pragma unroll
        for (int u = 0; u < 4; u++) {
            *(uint4*)(Ah + asw[u])         = *(const uint4*)(ah + u * 16);
            *(uint4*)(Ah + 16384 + asw[u]) = *(const uint4*)(al + u * 16);
        }
#pragma unroll
        for (int u = 0; u < 4; u++) {
            *(uint4*)(Ah + 32768 + tid * 64 + u * 16) = *(const uint4*)(bh + u * 16);
            *(uint4*)(Ah + 49152 + tid * 64 + u * 16) = *(const uint4*)(bl + u * 16);
        }
        FENCE_PROXY_ASYNC();
        __syncthreads();
        if (wid == 0 && elect_one_pred()) {
            uint32_t base = sb + 1024 + s * 65536;
            uint64_t dAh = MAKE_SMEM_DESC(base);
            uint64_t dAl = MAKE_SMEM_DESC(base + 16384);
            uint64_t dBh = MAKE_SMEM_DESC(base + 32768);
            uint64_t dBl = MAKE_SMEM_DESC(base + 49152);
#pragma unroll
            for (int ks = 0; ks < 4; ks++)
                mma_f16_ss(tmem, dAh + ks * 2, dBh + ks * 2, IDESC_128x128,
                           !(c == 0 && ks == 0));
#pragma unroll
            for (int ks = 0; ks < 4; ks++)
                mma_f16_ss(tmem, dAh + ks * 2, dBl + ks * 2, IDESC_128x128, true);
#pragma unroll
            for (int ks = 0; ks < 4; ks++)
                mma_f16_ss(tmem, dAl + ks * 2, dBh + ks * 2, IDESC_128x128, true);
            TCGEN05_COMMIT(sb + 8 + s * 8);
        }
    }
    mbar_wait(sb + 8,  ph[0]);
    mbar_wait(sb + 16, ph[1]);
    TCGEN05_FENCE_AFTER();

    {
        int sub = wid & 3, cg = wid >> 2;
        int m = m0 + sub * 32 + lid;
        uint32_t coff = (uint32_t)(cg * 64);
        uint32_t d0[32], d1[32];
        TCGEN05_LD_32X32B_X32(d0, tmem + coff);
        TCGEN05_LD_32X32B_X32(d1, tmem + coff + 32);
        TCGEN05_WAIT_LD();
        if (m < nrows) {
            float wsc = 1.f;
            float* dst;
            if (EMODE == 1) {
                int slot = seg + m;
                int tk = g_tk[slot];
                wsc = g_w[slot];
                dst = (float*)(g_scratch + O_PART) + (size_t)tk * HDIM
                      + (size_t)nb * 128 + coff;
            } else {
                float* ob = ext_out ? ext_out : (float*)(g_scratch + out_off);
                dst = ob + (size_t)(seg + m) * ND + (size_t)nb * 128 + coff;
            }
#pragma unroll
            for (int j = 0; j < 8; j++)
                *(float4*)(dst + 4 * j) = make_float4(
                    __uint_as_float(d0[4*j+0]) * wsc, __uint_as_float(d0[4*j+1]) * wsc,
                    __uint_as_float(d0[4*j+2]) * wsc, __uint_as_float(d0[4*j+3]) * wsc);
#pragma unroll
            for (int j = 0; j < 8; j++)
                *(float4*)(dst + 32 + 4 * j) = make_float4(
                    __uint_as_float(d1[4*j+0]) * wsc, __uint_as_float(d1[4*j+1]) * wsc,
                    __uint_as_float(d1[4*j+2]) * wsc, __uint_as_float(d1[4*j+3]) * wsc);
        }
    }
    __syncthreads();
    if (tid == 0) { MBARRIER_INVAL(sb + 8); MBARRIER_INVAL(sb + 16); }
    __syncthreads();
    if (wid == 0) TCGEN05_DEALLOC(tmem, 128);

#else
    // =======================================================================
    // mma.sync fallback path (generic sm_103 target)
    // Warp tile 32(M) x 64(N): 2 m16 frags x 8 n8 frags, 3 terms into one acc.
    // =======================================================================
    int wm = (wid & 3) * 32, wn = (wid >> 2) * 64;
    float acc[2][8][4];
#pragma unroll
    for (int a = 0; a < 2; a++)
#pragma unroll
        for (int b = 0; b < 8; b++)
#pragma unroll
            for (int c2 = 0; c2 < 4; c2++) acc[a][b][c2] = 0.f;

    // stage chunk c into buffer c&1 via cp.async
    auto stage = [&](int c) {
        int s = c & 1;
        uint32_t X = sb + 1024 + (uint32_t)s * 65536u;
        const char* ah = ah0 + (size_t)c * 128;
        const char* al = al0 + (size_t)c * 128;
        const char* bh = bh0 + (size_t)c * 16384;
        const char* bl = bl0 + (size_t)c * 16384;
#pragma unroll
        for (int u = 0; u < 4; u++) {
            cp16(X + asw[u],         ah + u * 16);
            cp16(X + 16384 + asw[u], al + u * 16);
        }
#pragma unroll
        for (int u = 0; u < 4; u++) {
            cp16(X + 32768 + tid * 64 + u * 16, bh + u * 16);
            cp16(X + 49152 + tid * 64 + u * 16, bl + u * 16);
        }
        asm volatile("cp.async.commit_group;");
    };

    auto compute = [&](int s) {
        uint32_t X = sb + 1024 + (uint32_t)s * 65536u;
#pragma unroll
        for (int k16 = 0; k16 < 4; k16++) {
            int kb = k16 * 32;
            int g = lid >> 3;
            uint32_t afh[2][4], afl[2][4];
#pragma unroll
            for (int mf = 0; mf < 2; mf++) {
                int rr = wm + mf * 16 + (lid & 7) + (g & 1) * 8;
                int bb = kb + (g >> 1) * 16;
                uint32_t ad = X + swz32((uint32_t)(rr * 128 + bb));
                ldsm_x4(afh[mf], ad);
                ldsm_x4(afl[mf], ad + 16384);
            }
            uint32_t bfh[8][2], bfl[8][2];
#pragma unroll
            for (int nq = 0; nq < 4; nq++) {
                int rr = wn + nq * 16 + (lid & 7) + (g >> 1) * 8;
                int bb = kb + (g & 1) * 16;
                uint32_t ad = X + 32768 + swz32((uint32_t)(rr * 128 + bb));
                uint32_t t4[4];
                ldsm_x4(t4, ad);
                bfh[2*nq][0] = t4[0]; bfh[2*nq][1] = t4[1];
                bfh[2*nq+1][0] = t4[2]; bfh[2*nq+1][1] = t4[3];
                ldsm_x4(t4, ad + 16384);
                bfl[2*nq][0] = t4[0]; bfl[2*nq][1] = t4[1];
                bfl[2*nq+1][0] = t4[2]; bfl[2*nq+1][1] = t4[3];
            }
#pragma unroll
            for (int mf = 0; mf < 2; mf++)
#pragma unroll
                for (int nf = 0; nf < 8; nf++) {
                    mma_bf16(acc[mf][nf], afh[mf], bfh[nf]);
                    mma_bf16(acc[mf][nf], afh[mf], bfl[nf]);
                    mma_bf16(acc[mf][nf], afl[mf], bfh[nf]);
                }
        }
    };

    stage(0);
    for (int c = 0; c < KC; c++) {
        if (c + 1 < KC) {
            stage(c + 1);
            asm volatile("cp.async.wait_group 1;");
        } else {
            asm volatile("cp.async.wait_group 0;");
        }
        __syncthreads();
        compute(c & 1);
        __syncthreads();
    }

    // epilogue
#pragma unroll
    for (int mf = 0; mf < 2; mf++) {
        int r0 = m0 + wm + mf * 16 + (lid >> 2);
#pragma unroll
        for (int hh = 0; hh < 2; hh++) {
            int rr = r0 + hh * 8;
            if (rr - m0 >= 128 || rr >= nrows) continue;
            float wsc = 1.f;
            float* dst;
            if (EMODE == 1) {
                int slot = seg + rr;
                int tk = g_tk[slot];
                wsc = g_w[slot];
                dst = (float*)(g_scratch + O_PART) + (size_t)tk * HDIM + (size_t)nb * 128;
            } else {
                float* ob = ext_out ? ext_out : (float*)(g_scratch + out_off);
                dst = ob + (size_t)(seg + rr) * ND + (size_t)nb * 128;
            }
#pragma unroll
            for (int nf = 0; nf < 8; nf++) {
                int col = wn + nf * 8 + (lid & 3) * 2;
                float2 v;
                v.x = acc[mf][nf][hh * 2 + 0] * wsc;
                v.y = acc[mf][nf][hh * 2 + 1] * wsc;
                *(float2*)(dst + col) = v;
            }
        }
    }
#endif
}

// ---------------------------------------------------------------------------
// combine
// ---------------------------------------------------------------------------
__global__ void combine_kernel(float* __restrict__ out) {
    size_t i = (size_t)blockIdx.x * blockDim.x + threadIdx.x;
    size_t v = i * 4;
    int t = (int)(v / HDIM);
    int h = (int)(v % HDIM);
    const float* part = (const float*)(g_scratch + O_PART);
    float4 o = *(float4*)&out[v];
#pragma unroll
    for (int k = 0; k < TOPK; k++) {
        const float4 p = *(const float4*)&part[(size_t)(t * TOPK + k) * HDIM + h];
        o.x += p.x; o.y += p.y; o.z += p.z; o.w += p.w;
    }
    *(float4*)&out[v] = o;
}

// ---------------------------------------------------------------------------
// launch
// ---------------------------------------------------------------------------
extern "C" void kernel_launch(void* const* d_in, const int* in_sizes, int n_in,
                              void* d_out, int out_size) {
    const float* hidden      = (const float*)d_in[0];
    const float* gate_weight = (const float*)d_in[1];
    const float* bias        = (const float*)d_in[2];
    const float* gate_w      = (const float*)d_in[3];
    const float* up_w        = (const float*)d_in[4];
    const float* down_w      = (const float*)d_in[5];
    const float* sh_gate_w   = (const float*)d_in[6];
    const float* sh_up_w     = (const float*)d_in[7];
    const float* sh_down_w   = (const float*)d_in[8];
    float* out = (float*)d_out;

    cudaFuncSetAttribute(mma_gemm<2048, 1024, 1, 0>,
                         cudaFuncAttributeMaxDynamicSharedMemorySize, GSMEM_BYTES);
    cudaFuncSetAttribute(mma_gemm<1024, 2048, 2, 1>,
                         cudaFuncAttributeMaxDynamicSharedMemorySize, GSMEM_BYTES);
    cudaFuncSetAttribute(mma_gemm<2048, 2048, 0, 0>,
                         cudaFuncAttributeMaxDynamicSharedMemorySize, GSMEM_BYTES);

    // ---- preconversion ----
    {
        int np = NEXP * FMOE * HDIM / 2;
        prep_weight<FMOE, HDIM><<<(np + 255) / 256, 256>>>(gate_w, O_WG_HI, O_WG_LO, np);
        prep_weight<FMOE, HDIM><<<(np + 255) / 256, 256>>>(up_w,   O_WU_HI, O_WU_LO, np);
    }
    {
        int np = NEXP * HDIM * FMOE / 2;
        prep_weight<HDIM, FMOE><<<(np + 255) / 256, 256>>>(down_w, O_WD_HI, O_WD_LO, np);
    }
    {
        int np = FSH * HDIM / 2;
        prep_weight<FSH, HDIM><<<(np + 255) / 256, 256>>>(sh_gate_w, O_WSG_HI, O_WSG_LO, np);
        prep_weight<FSH, HDIM><<<(np + 255) / 256, 256>>>(sh_up_w,   O_WSU_HI, O_WSU_LO, np);
        prep_weight<HDIM, FSH><<<(np + 255) / 256, 256>>>(sh_down_w, O_WSD_HI, O_WSD_LO, np);
    }
    {
        int np = T_TOK * HDIM / 2;
        prep_split<<<(np + 255) / 256, 256>>>(hidden, O_HID_HI, O_HID_LO, np);
    }

    // ---- routing ----
    zero_kernel<<<1, 32>>>();
    router_kernel<<<T_TOK, 512>>>(hidden, gate_weight, bias);
    offsets_kernel<<<1, 1>>>();
    dispatch_kernel<<<(T_TOK + 255) / 256, 256>>>();

    // ---- routed experts ----
    mma_gemm<2048, 1024, 1, 0><<<dim3(FMOE / 128, T_TOK / 128, NEXP), 256, GSMEM_BYTES>>>(
        O_HID_HI, O_HID_LO, O_WG_HI, O_WG_LO, O_GBUF, nullptr);
    mma_gemm<2048, 1024, 1, 0><<<dim3(FMOE / 128, T_TOK / 128, NEXP), 256, GSMEM_BYTES>>>(
        O_HID_HI, O_HID_LO, O_WU_HI, O_WU_LO, O_UBUF, nullptr);
    {
        int np = NASS * FMOE / 2;
        act_kernel<<<(np + 255) / 256, 256>>>(O_GBUF, O_UBUF, O_ACT_HI, O_ACT_LO, np);
    }
    mma_gemm<1024, 2048, 2, 1><<<dim3(HDIM / 128, T_TOK / 128, NEXP), 256, GSMEM_BYTES>>>(
        O_ACT_HI, O_ACT_LO, O_WD_HI, O_WD_LO, 0, nullptr);

    // ---- shared expert ----
    mma_gemm<2048, 2048, 0, 0><<<dim3(FSH / 128, T_TOK / 128, 1), 256, GSMEM_BYTES>>>(
        O_HID_HI, O_HID_LO, O_WSG_HI, O_WSG_LO, O_SHG, nullptr);
    mma_gemm<2048, 2048, 0, 0><<<dim3(FSH / 128, T_TOK / 128, 1), 256, GSMEM_BYTES>>>(
        O_HID_HI, O_HID_LO, O_WSU_HI, O_WSU_LO, O_SHU, nullptr);
    {
        int np = T_TOK * FSH / 2;
        act_kernel<<<(np + 255) / 256, 256>>>(O_SHG, O_SHU, O_SHA_HI, O_SHA_LO, np);
    }
    mma_gemm<2048, 2048, 0, 0><<<dim3(HDIM / 128, T_TOK / 128, 1), 256, GSMEM_BYTES>>>(
        O_SHA_HI, O_SHA_LO, O_WSD_HI, O_WSD_LO, 0, out);

    // ---- combine ----
    combine_kernel<<<(T_TOK * HDIM / 4) / 256, 256>>>(out);
}